// round 5
// baseline (speedup 1.0000x reference)
#include <cuda_runtime.h>

// Problem constants (pred_softmax: (16, 11, 1, 512, 512) fp32)
#define BDIM   16
#define PDIM   11
#define PM1    10
#define HDIM   512
#define WDIM   512
#define NMAPS  (BDIM * PM1)        // 160
#define CHUNKS 8
#define NBLK   (NMAPS * CHUNKS)    // 1280
#define THREADS 256
#define ROWS_PER_CHUNK (HDIM / CHUNKS)              // 64
#define F4_PER_CHUNK   (ROWS_PER_CHUNK * WDIM / 4)  // 8192
#define ITERS  (F4_PER_CHUNK / THREADS)             // 32
#define UNROLL 4

// Deterministic scratch: [block][5] = {S, Sx, Sy, Sxx, Syy}
__device__ float g_part[NBLK * 5];
__device__ unsigned int g_count;   // zero-init at load; reset by last block

__global__ void __launch_bounds__(THREADS, 8)
moments_fused(const float* __restrict__ in, float* __restrict__ out)
{
    const int blk   = blockIdx.x;
    const int map   = blk / CHUNKS;
    const int chunk = blk % CHUNKS;
    const int b = map / PM1;
    const int p = map % PM1;

    const size_t map_off = (size_t)(b * PDIM + p) * (size_t)(HDIM * WDIM);
    const float4* __restrict__ src =
        (const float4*)(in + map_off + (size_t)chunk * ROWS_PER_CHUNK * WDIM);

    const float c  = 2.0f / (float)WDIM;   // 1/256
    const int tid  = threadIdx.x;

    // Thread geometry: stride THREADS over 128-f4 rows ->
    //   column (tid & 127) is INVARIANT; row advances by 2 each iteration.
    const float dy = 2.0f * c;                                   // row step per iter (2 rows)
    float ym = (float)(chunk * ROWS_PER_CHUNK + (tid >> 7)) * c - 1.0f;

    // Column-invariant accumulators: plain sums of the 4 lanes of the f4,
    // plus y-weighted sums. x-weighting folded in AFTER the loop.
    float Ax = 0.f, Ay = 0.f, Az = 0.f, Aw = 0.f;
    float Sy = 0.f, Syy = 0.f;

    #pragma unroll
    for (int j = 0; j < ITERS; j += UNROLL) {
        float4 v[UNROLL];
        #pragma unroll
        for (int u = 0; u < UNROLL; u++)
            v[u] = __ldcs(&src[tid + (j + u) * THREADS]);

        #pragma unroll
        for (int u = 0; u < UNROLL; u++) {
            Ax += v[u].x;  Ay += v[u].y;  Az += v[u].z;  Aw += v[u].w;
            const float s4  = (v[u].x + v[u].y) + (v[u].z + v[u].w);
            const float ymu = fmaf((float)u, dy, ym);
            const float t   = s4 * ymu;
            Sy  += t;
            Syy  = fmaf(t, ymu, Syy);
        }
        ym += (float)UNROLL * dy;
    }

    // Fold x-weighting in once per thread (column is fixed).
    const float x0 = (float)((tid & 127) * 4) * c - 1.0f;
    const float x1 = x0 + c;
    const float x2 = x0 + 2.0f * c;
    const float x3 = x0 + 3.0f * c;
    float S   = (Ax + Ay) + (Az + Aw);
    float Sx  = fmaf(Ax, x0, fmaf(Ay, x1, fmaf(Az, x2, Aw * x3)));
    float Sxx = fmaf(Ax, x0 * x0, fmaf(Ay, x1 * x1, fmaf(Az, x2 * x2, Aw * (x3 * x3))));

    // warp reduce (fixed order -> deterministic)
    #pragma unroll
    for (int o = 16; o; o >>= 1) {
        S   += __shfl_xor_sync(0xffffffffu, S,   o);
        Sx  += __shfl_xor_sync(0xffffffffu, Sx,  o);
        Sy  += __shfl_xor_sync(0xffffffffu, Sy,  o);
        Sxx += __shfl_xor_sync(0xffffffffu, Sxx, o);
        Syy += __shfl_xor_sync(0xffffffffu, Syy, o);
    }

    __shared__ float sm[THREADS / 32][5];
    const int wid = tid >> 5, lid = tid & 31;
    if (lid == 0) {
        sm[wid][0] = S; sm[wid][1] = Sx; sm[wid][2] = Sy;
        sm[wid][3] = Sxx; sm[wid][4] = Syy;
    }
    __syncthreads();

    if (tid < 5) {
        float acc = 0.f;
        #pragma unroll
        for (int w = 0; w < THREADS / 32; w++) acc += sm[w][tid];
        g_part[blk * 5 + tid] = acc;
    }

    // ---- last-block final reduction ----
    __threadfence();
    __shared__ unsigned int s_ticket;
    if (tid == 0) s_ticket = atomicAdd(&g_count, 1u);
    __syncthreads();
    if (s_ticket != NBLK - 1) return;

    if (tid == 0) g_count = 0;   // reset for next graph replay

    float v = 0.f;
    if (tid < NMAPS) {
        float a0 = 0.f, a1 = 0.f, a2 = 0.f, a3 = 0.f, a4 = 0.f;
        #pragma unroll
        for (int cch = 0; cch < CHUNKS; cch++) {
            const int base = (tid * CHUNKS + cch) * 5;
            a0 += g_part[base + 0];
            a1 += g_part[base + 1];
            a2 += g_part[base + 2];
            a3 += g_part[base + 3];
            a4 += g_part[base + 4];
        }
        const float k   = a0 + 1e-8f;
        const float inv = 1.0f / k;
        const float xc  = a1 * inv;
        const float yc  = a2 * inv;
        const float vx = (a3 - 2.0f * xc * a1 + xc * xc * a0) * inv;
        const float vy = (a4 - 2.0f * yc * a2 + yc * yc * a0) * inv;
        v = vx + vy;
    }

    #pragma unroll
    for (int o = 16; o; o >>= 1) v += __shfl_xor_sync(0xffffffffu, v, o);

    __shared__ float sm2[THREADS / 32];
    if ((tid & 31) == 0) sm2[tid >> 5] = v;
    __syncthreads();

    if (tid == 0) {
        float t = 0.f;
        #pragma unroll
        for (int i = 0; i < THREADS / 32; i++) t += sm2[i];
        out[0] = t / (float)BDIM;
    }
}

extern "C" void kernel_launch(void* const* d_in, const int* in_sizes, int n_in,
                              void* d_out, int out_size)
{
    const float* pred = (const float*)d_in[0];
    float* out = (float*)d_out;
    (void)in_sizes; (void)n_in; (void)out_size;

    moments_fused<<<NBLK, THREADS>>>(pred, out);
}